// round 12
// baseline (speedup 1.0000x reference)
#include <cuda_runtime.h>
#include <cuda_fp16.h>
#include <math.h>
#include <stdint.h>

#define NN 10000
#define DD 512
#define HH 256
#define OO 128
#define CAP 128          // final merged neighbor cap per row
#define CAPH 96          // cap per half (upper / lower)
#define LCAP 16          // per-lane local buffer in scan

// ---------------- scratch (static device memory; no allocations) -------------
__device__ int      g_cols [(size_t)NN * CAP];    // merged neighbor lists
__device__ int      g_cnt  [NN];                  // merged nnz per row
__device__ float    g_dinv [NN];                  // rsqrt(degree)
__device__ uint32_t g_dinvh2[NN];                 // (dinv, dinv) packed half2
__device__ int      g_colsU[(size_t)NN * CAPH];   // upper-tri neighbors (own scan)
__device__ int      g_cntU [NN];
__device__ int      g_colsL[(size_t)NN * CAPH];   // lower-tri neighbors (atomic scatter)
__device__ int      g_cntL [NN];
__device__ __half   g_xw  [(size_t)NN * HH];      // x @ W1 (UNscaled), fp16
__device__ __half   g_h   [(size_t)NN * HH];      // hs = dinv .* relu(an @ xw), fp16
__device__ float    g_g   [(size_t)NN * HH];      // g  = an @ h, fp32

// ---------------- Kernel A: upper-triangle scan, warp-per-row ----------------
__global__ __launch_bounds__(256)
void k_scan_ut(const float* __restrict__ adj)
{
    const int lane = threadIdx.x & 31;
    const int row  = blockIdx.x * 8 + (threadIdx.x >> 5);
    const uint32_t* __restrict__ arow =
        reinterpret_cast<const uint32_t*>(adj + (size_t)row * NN);

    int local[LCAP];
    int lc = 0;

    const int start = row + 1;
    int aligned = (start + 15) & ~15;
    if (aligned > NN) aligned = NN;

    {
        int c = start + lane;
        if (c < aligned && arow[c] != 0u) { local[lc] = c; lc++; }
    }

    const uint4* __restrict__ arow4 = reinterpret_cast<const uint4*>(arow);
    const int base = aligned >> 4;
    const int nch  = NN >> 4;
    for (int t = base + lane; t < nch; t += 32) {
        const uint4* p = arow4 + 4 * t;
        uint4 w0 = p[0], w1 = p[1], w2 = p[2], w3 = p[3];
        uint32_t m = ((w0.x | w0.y) | (w0.z | w0.w))
                   | ((w1.x | w1.y) | (w1.z | w1.w))
                   | ((w2.x | w2.y) | (w2.z | w2.w))
                   | ((w3.x | w3.y) | (w3.z | w3.w));
        if (m != 0u) {
            const int c0 = t << 4;
            #define CHK(w, off) if ((w) != 0u) { if (lc < LCAP) local[lc] = c0 + (off); lc++; }
            CHK(w0.x, 0)  CHK(w0.y, 1)  CHK(w0.z, 2)  CHK(w0.w, 3)
            CHK(w1.x, 4)  CHK(w1.y, 5)  CHK(w1.z, 6)  CHK(w1.w, 7)
            CHK(w2.x, 8)  CHK(w2.y, 9)  CHK(w2.z, 10) CHK(w2.w, 11)
            CHK(w3.x, 12) CHK(w3.y, 13) CHK(w3.z, 14) CHK(w3.w, 15)
            #undef CHK
        }
    }
    if (lc > LCAP) lc = LCAP;

    int inc = lc;
    #pragma unroll
    for (int d = 1; d < 32; d <<= 1) {
        int n = __shfl_up_sync(0xffffffffu, inc, d);
        if (lane >= d) inc += n;
    }
    const int pos   = inc - lc;
    const int total = __shfl_sync(0xffffffffu, inc, 31);

    int* __restrict__ ucols = g_colsU + (size_t)row * CAPH;
    for (int i = 0; i < lc; i++) {
        int c = local[i];
        int p = pos + i;
        if (p < CAPH) ucols[p] = c;
        int lp = atomicAdd(&g_cntL[c], 1);
        if (lp < CAPH) g_colsL[(size_t)c * CAPH + lp] = row;
    }
    if (lane == 0) {
        int t = total;
        if (t > CAPH) t = CAPH;
        g_cntU[row] = t;
    }
}

// ---------------- Kernel M: merge L (sorted) + U -> g_cols, cnt, dinv --------
__global__ __launch_bounds__(256)
void k_merge()
{
    const int lane = threadIdx.x & 31;
    const int row  = blockIdx.x * 8 + (threadIdx.x >> 5);
    if (row >= NN) return;

    int cntL = g_cntL[row]; if (cntL > CAPH) cntL = CAPH;
    int cntU = g_cntU[row]; if (cntU > CAPH) cntU = CAPH;
    int total = cntL + cntU; if (total > CAP) total = CAP;

    const int* __restrict__ L = g_colsL + (size_t)row * CAPH;
    const int* __restrict__ U = g_colsU + (size_t)row * CAPH;
    int* __restrict__ dst = g_cols + (size_t)row * CAP;

    for (int s = lane; s < cntL; s += 32) {
        int v = L[s];
        int rank = 0;
        for (int j = 0; j < cntL; j++) rank += (L[j] < v) ? 1 : 0;
        if (rank < CAP) dst[rank] = v;
    }
    for (int k = lane; k < cntU; k += 32) {
        int p = cntL + k;
        if (p < CAP) dst[p] = U[k];
    }
    if (lane == 0) {
        float d = rsqrtf((float)total + 1.0f);
        g_cnt[row]  = total;
        g_dinv[row] = d;
        __half2 dh = __floats2half2_rn(d, d);
        g_dinvh2[row] = *reinterpret_cast<uint32_t*>(&dh);
    }
}

// ---------------- tf32 helpers ----------------
__device__ __forceinline__ uint32_t f2tf32(float x)
{
    uint32_t r;
    asm("cvt.rna.tf32.f32 %0, %1;" : "=r"(r) : "f"(x));
    return r;
}

__device__ __forceinline__ void mma_tf32(float c[4],
    uint32_t a0, uint32_t a1, uint32_t a2, uint32_t a3,
    uint32_t b0, uint32_t b1)
{
    asm volatile(
        "mma.sync.aligned.m16n8k8.row.col.f32.tf32.tf32.f32 "
        "{%0,%1,%2,%3}, {%4,%5,%6,%7}, {%8,%9}, {%0,%1,%2,%3};"
        : "+f"(c[0]), "+f"(c[1]), "+f"(c[2]), "+f"(c[3])
        : "r"(a0), "r"(a1), "r"(a2), "r"(a3), "r"(b0), "r"(b1));
}

__device__ __forceinline__ int swz(int k)
{
    return ((k & 3) ^ ((k >> 2) & 3)) << 3;
}

// ---------------- Kernel B: tf32 tensor-core GEMM  (R4 proven config) -------
template<int KDIM, bool SCALE_DINV, bool DUAL_B, bool OUT_HALF>
__global__ __launch_bounds__(128)
void k_mma(const float* __restrict__ A, const float* __restrict__ Bm,
           const float* __restrict__ Bs2, void* __restrict__ Cv,
           int M, int NDIM)
{
    const int BM = 128, BN = 128, BK = 16;
    const int NIT = KDIM / BK;
    __shared__ uint32_t As[2][BK * BM];
    __shared__ uint32_t Bsm[2][BK * BN];

    const int tid  = threadIdx.x;
    const int lane = tid & 31;
    const int warp = tid >> 5;
    const int wm   = warp >> 1;
    const int wn   = warp & 1;
    const int gid  = lane >> 2;
    const int tig  = lane & 3;

    const int row0 = blockIdx.y * BM;
    const float* __restrict__ B = DUAL_B ? (blockIdx.x ? Bs2 : Bm) : Bm;
    const int col0 = DUAL_B ? 0 : blockIdx.x * BN;
    const size_t coff = DUAL_B ? (size_t)blockIdx.x * (size_t)M * NDIM : 0;

    const int a_m  = tid >> 2;
    const int a_kq = tid & 3;
    const int b_k  = tid >> 3;
    const int b_n4 = (tid & 7) * 4;

    float acc[4][8][4];
    #pragma unroll
    for (int mt = 0; mt < 4; mt++)
        #pragma unroll
        for (int nt = 0; nt < 8; nt++)
            #pragma unroll
            for (int i = 0; i < 4; i++) acc[mt][nt][i] = 0.0f;

    float4 ra[4], rb[4];

    #pragma unroll
    for (int j = 0; j < 4; j++) {
        int m = a_m + 32 * j;
        int gr = row0 + m;
        ra[j] = (gr < M)
            ? *reinterpret_cast<const float4*>(A + (size_t)gr * KDIM + a_kq * 4)
            : make_float4(0.f, 0.f, 0.f, 0.f);
        rb[j] = *reinterpret_cast<const float4*>(B + (size_t)b_k * NDIM + col0 + b_n4 + 32 * j);
    }
    {
        #pragma unroll
        for (int j = 0; j < 4; j++) {
            int m = a_m + 32 * j;
            const float* v = &ra[j].x;
            #pragma unroll
            for (int i = 0; i < 4; i++) {
                int k = a_kq * 4 + i;
                As[0][k * BM + (m ^ swz(k))] = f2tf32(v[i]);
            }
            int n = b_n4 + 32 * j;
            const float* w = &rb[j].x;
            uint32_t* dst = &Bsm[0][b_k * BN + (n ^ swz(b_k))];
            #pragma unroll
            for (int i = 0; i < 4; i++) dst[i] = f2tf32(w[i]);
        }
    }
    __syncthreads();

    int st = 0;
    for (int it = 0; it < NIT; ++it) {
        if (it + 1 < NIT) {
            int k0 = (it + 1) * BK;
            #pragma unroll
            for (int j = 0; j < 4; j++) {
                int m = a_m + 32 * j;
                int gr = row0 + m;
                ra[j] = (gr < M)
                    ? *reinterpret_cast<const float4*>(A + (size_t)gr * KDIM + k0 + a_kq * 4)
                    : make_float4(0.f, 0.f, 0.f, 0.f);
                rb[j] = *reinterpret_cast<const float4*>(B + (size_t)(k0 + b_k) * NDIM + col0 + b_n4 + 32 * j);
            }
        }

        #pragma unroll
        for (int ks = 0; ks < BK; ks += 8) {
            const int k1 = ks + tig;
            const int k2 = ks + tig + 4;
            const int sx1 = swz(k1);
            const int sx2 = swz(k2);

            uint32_t af[4][4];
            #pragma unroll
            for (int mt = 0; mt < 4; mt++) {
                int r1 = wm * 64 + mt * 16 + gid;
                af[mt][0] = As[st][k1 * BM + (r1 ^ sx1)];
                af[mt][1] = As[st][k1 * BM + ((r1 + 8) ^ sx1)];
                af[mt][2] = As[st][k2 * BM + (r1 ^ sx2)];
                af[mt][3] = As[st][k2 * BM + ((r1 + 8) ^ sx2)];
            }
            uint32_t bf[8][2];
            #pragma unroll
            for (int nt = 0; nt < 8; nt++) {
                int cn = wn * 64 + nt * 8 + gid;
                bf[nt][0] = Bsm[st][k1 * BN + (cn ^ sx1)];
                bf[nt][1] = Bsm[st][k2 * BN + (cn ^ sx2)];
            }
            #pragma unroll
            for (int mt = 0; mt < 4; mt++)
                #pragma unroll
                for (int nt = 0; nt < 8; nt++)
                    mma_tf32(acc[mt][nt], af[mt][0], af[mt][1], af[mt][2], af[mt][3],
                             bf[nt][0], bf[nt][1]);
        }

        if (it + 1 < NIT) {
            int so = st ^ 1;
            #pragma unroll
            for (int j = 0; j < 4; j++) {
                int m = a_m + 32 * j;
                const float* v = &ra[j].x;
                #pragma unroll
                for (int i = 0; i < 4; i++) {
                    int k = a_kq * 4 + i;
                    As[so][k * BM + (m ^ swz(k))] = f2tf32(v[i]);
                }
                int n = b_n4 + 32 * j;
                const float* w = &rb[j].x;
                uint32_t* dst = &Bsm[so][b_k * BN + (n ^ swz(b_k))];
                #pragma unroll
                for (int i = 0; i < 4; i++) dst[i] = f2tf32(w[i]);
            }
            __syncthreads();
            st = so;
        }
    }

    // ---- epilogue ----
    #pragma unroll
    for (int mt = 0; mt < 4; mt++) {
        int r1 = row0 + wm * 64 + mt * 16 + gid;
        int r2 = r1 + 8;
        float s1 = 1.0f, s2 = 1.0f;
        if (SCALE_DINV) {
            if (r1 < M) s1 = g_dinv[r1];
            if (r2 < M) s2 = g_dinv[r2];
        }
        #pragma unroll
        for (int nt = 0; nt < 8; nt++) {
            int col = col0 + wn * 64 + nt * 8 + tig * 2;
            if (r1 < M) {
                if (OUT_HALF) {
                    __half2 v = __floats2half2_rn(acc[mt][nt][0] * s1, acc[mt][nt][1] * s1);
                    *reinterpret_cast<__half2*>((__half*)Cv + coff + (size_t)r1 * NDIM + col) = v;
                } else {
                    float2 v = make_float2(acc[mt][nt][0] * s1, acc[mt][nt][1] * s1);
                    *reinterpret_cast<float2*>((float*)Cv + coff + (size_t)r1 * NDIM + col) = v;
                }
            }
            if (r2 < M) {
                if (OUT_HALF) {
                    __half2 v = __floats2half2_rn(acc[mt][nt][2] * s2, acc[mt][nt][3] * s2);
                    *reinterpret_cast<__half2*>((__half*)Cv + coff + (size_t)r2 * NDIM + col) = v;
                } else {
                    float2 v = make_float2(acc[mt][nt][2] * s2, acc[mt][nt][3] * s2);
                    *reinterpret_cast<float2*>((float*)Cv + coff + (size_t)r2 * NDIM + col) = v;
                }
            }
        }
    }
}

// ---------------- Kernel C1: weighted SpMM (layer 1) -------------------------
// X = xw UNscaled fp16. acc = sum_{j in N+(i)} dinv_j * u_j  (self included),
// out (fp16) = dinv_i * relu(dinv_i * acc)  — prescaled for the next layer.
// Neighbor dinv staged in smem as packed half2; chunk of 4 = hmul2 + 3 hfma2.
__global__ __launch_bounds__(256)
void k_spmm_w(const uint2* __restrict__ X, uint2* __restrict__ Y)
{
    const int sub  = threadIdx.x >> 6;
    const int lane = threadIdx.x & 63;
    const int row  = blockIdx.x * 4 + sub;

    __shared__ int      s_cols[4][CAP];
    __shared__ uint32_t s_d[4][CAP];
    const int cnt = g_cnt[row];
    {
        const int* __restrict__ cols = g_cols + (size_t)row * CAP;
        for (int k = lane; k < cnt; k += 64) {
            int c = cols[k];
            s_cols[sub][k] = c;
            s_d[sub][k]    = g_dinvh2[c];
        }
    }
    __syncthreads();

    const int* __restrict__ sc = s_cols[sub];
    const uint32_t* __restrict__ sd = s_d[sub];
    const int HV = HH / 4;

    const float di = g_dinv[row];

    // self term: dinv_i * u_i, accumulated in fp32
    float2 acc0, acc1;
    {
        uint2 u = X[(size_t)row * HV + lane];
        float2 f0 = __half22float2(*reinterpret_cast<__half2*>(&u.x));
        float2 f1 = __half22float2(*reinterpret_cast<__half2*>(&u.y));
        acc0 = make_float2(di * f0.x, di * f0.y);
        acc1 = make_float2(di * f1.x, di * f1.y);
    }

    int k = 0;
    for (; k + 4 <= cnt; k += 4) {
        uint2 u0 = X[(size_t)sc[k]     * HV + lane];
        uint2 u1 = X[(size_t)sc[k + 1] * HV + lane];
        uint2 u2 = X[(size_t)sc[k + 2] * HV + lane];
        uint2 u3 = X[(size_t)sc[k + 3] * HV + lane];
        uint32_t w0 = sd[k], w1 = sd[k + 1], w2 = sd[k + 2], w3 = sd[k + 3];
        __half2 d0 = *reinterpret_cast<__half2*>(&w0);
        __half2 d1 = *reinterpret_cast<__half2*>(&w1);
        __half2 d2 = *reinterpret_cast<__half2*>(&w2);
        __half2 d3 = *reinterpret_cast<__half2*>(&w3);

        __half2 s0 = __hmul2(*reinterpret_cast<__half2*>(&u0.x), d0);
        s0 = __hfma2(*reinterpret_cast<__half2*>(&u1.x), d1, s0);
        s0 = __hfma2(*reinterpret_cast<__half2*>(&u2.x), d2, s0);
        s0 = __hfma2(*reinterpret_cast<__half2*>(&u3.x), d3, s0);

        __half2 s1 = __hmul2(*reinterpret_cast<__half2*>(&u0.y), d0);
        s1 = __hfma2(*reinterpret_cast<__half2*>(&u1.y), d1, s1);
        s1 = __hfma2(*reinterpret_cast<__half2*>(&u2.y), d2, s1);
        s1 = __hfma2(*reinterpret_cast<__half2*>(&u3.y), d3, s1);

        float2 f0 = __half22float2(s0);
        float2 f1 = __half22float2(s1);
        acc0.x += f0.x; acc0.y += f0.y;
        acc1.x += f1.x; acc1.y += f1.y;
    }
    for (; k < cnt; k++) {
        uint2 u = X[(size_t)sc[k] * HV + lane];
        uint32_t w = sd[k];
        __half2 d = *reinterpret_cast<__half2*>(&w);
        float2 f0 = __half22float2(__hmul2(*reinterpret_cast<__half2*>(&u.x), d));
        float2 f1 = __half22float2(__hmul2(*reinterpret_cast<__half2*>(&u.y), d));
        acc0.x += f0.x; acc0.y += f0.y;
        acc1.x += f1.x; acc1.y += f1.y;
    }

    float o0 = di * fmaxf(di * acc0.x, 0.0f);
    float o1 = di * fmaxf(di * acc0.y, 0.0f);
    float o2 = di * fmaxf(di * acc1.x, 0.0f);
    float o3 = di * fmaxf(di * acc1.y, 0.0f);
    uint2 o;
    *reinterpret_cast<__half2*>(&o.x) = __floats2half2_rn(o0, o1);
    *reinterpret_cast<__half2*>(&o.y) = __floats2half2_rn(o2, o3);
    Y[(size_t)row * HV + lane] = o;
}

// ---------------- Kernel C2: pure-add SpMM (layer 2, prescaled input) --------
__global__ __launch_bounds__(256)
void k_spmm_a(const uint2* __restrict__ X, float4* __restrict__ Y)
{
    const int sub  = threadIdx.x >> 6;
    const int lane = threadIdx.x & 63;
    const int row  = blockIdx.x * 4 + sub;

    __shared__ int s_cols[4][CAP];
    const int cnt = g_cnt[row];
    {
        const int* __restrict__ cols = g_cols + (size_t)row * CAP;
        for (int k = lane; k < cnt; k += 64) s_cols[sub][k] = cols[k];
    }
    __syncthreads();

    const int* __restrict__ sc = s_cols[sub];
    const int HV = HH / 4;

    float2 acc0, acc1;
    {
        uint2 u = X[(size_t)row * HV + lane];
        acc0 = __half22float2(*reinterpret_cast<__half2*>(&u.x));
        acc1 = __half22float2(*reinterpret_cast<__half2*>(&u.y));
    }

    int k = 0;
    for (; k + 4 <= cnt; k += 4) {
        uint2 u0 = X[(size_t)sc[k]     * HV + lane];
        uint2 u1 = X[(size_t)sc[k + 1] * HV + lane];
        uint2 u2 = X[(size_t)sc[k + 2] * HV + lane];
        uint2 u3 = X[(size_t)sc[k + 3] * HV + lane];
        __half2 s0 = __hadd2(__hadd2(*reinterpret_cast<__half2*>(&u0.x),
                                     *reinterpret_cast<__half2*>(&u1.x)),
                             __hadd2(*reinterpret_cast<__half2*>(&u2.x),
                                     *reinterpret_cast<__half2*>(&u3.x)));
        __half2 s1 = __hadd2(__hadd2(*reinterpret_cast<__half2*>(&u0.y),
                                     *reinterpret_cast<__half2*>(&u1.y)),
                             __hadd2(*reinterpret_cast<__half2*>(&u2.y),
                                     *reinterpret_cast<__half2*>(&u3.y)));
        float2 f0 = __half22float2(s0);
        float2 f1 = __half22float2(s1);
        acc0.x += f0.x; acc0.y += f0.y;
        acc1.x += f1.x; acc1.y += f1.y;
    }
    for (; k < cnt; k++) {
        uint2 u = X[(size_t)sc[k] * HV + lane];
        float2 f0 = __half22float2(*reinterpret_cast<__half2*>(&u.x));
        float2 f1 = __half22float2(*reinterpret_cast<__half2*>(&u.y));
        acc0.x += f0.x; acc0.y += f0.y;
        acc1.x += f1.x; acc1.y += f1.y;
    }

    const float di = g_dinv[row];
    Y[(size_t)row * HV + lane] =
        make_float4(di * acc0.x, di * acc0.y, di * acc1.x, di * acc1.y);
}

// ---------------- launch ----------------
extern "C" void kernel_launch(void* const* d_in, const int* in_sizes, int n_in,
                              void* d_out, int out_size)
{
    const float* adj = (const float*)d_in[0];   // [N, N]
    const float* x   = (const float*)d_in[1];   // [N, D]
    const float* W1  = (const float*)d_in[2];   // [D, H]
    const float* Wm  = (const float*)d_in[3];   // [H, O]
    const float* Ws  = (const float*)d_in[4];   // [H, O]
    float* out = (float*)d_out;                 // [2, N, O]

    __half* xw; cudaGetSymbolAddress((void**)&xw, g_xw);
    __half* h;  cudaGetSymbolAddress((void**)&h,  g_h);
    float*  g;  cudaGetSymbolAddress((void**)&g,  g_g);
    int*    cntL; cudaGetSymbolAddress((void**)&cntL, g_cntL);

    const int mtiles = (NN + 127) / 128;        // 79

    // fresh stream/events each call (host-side only; not destroyed to avoid
    // invalidating an in-progress capture — a handful of calls total)
    cudaStream_t s2;
    cudaEvent_t evFork, evJoin;
    cudaStreamCreateWithFlags(&s2, cudaStreamNonBlocking);
    cudaEventCreateWithFlags(&evFork, cudaEventDisableTiming);
    cudaEventCreateWithFlags(&evJoin, cudaEventDisableTiming);

    // ---- fork: mma1 (graph-independent) on side stream ----
    cudaEventRecord(evFork, 0);
    cudaStreamWaitEvent(s2, evFork, 0);
    // xw = x @ W1 (unscaled) -> fp16
    k_mma<DD, false, false, true><<<dim3(HH / 128, mtiles), 128, 0, s2>>>(
        x, W1, nullptr, xw, NN, HH);
    cudaEventRecord(evJoin, s2);

    // ---- main stream: graph preprocessing (concurrent with mma1) ----
    cudaMemsetAsync(cntL, 0, NN * sizeof(int));
    k_scan_ut<<<NN / 8, 256>>>(adj);
    k_merge<<<(NN + 7) / 8, 256>>>();

    // ---- join ----
    cudaStreamWaitEvent(0, evJoin, 0);

    // hs = dinv .* relu(an @ xw) -> fp16  (dinv folded into the gather)
    k_spmm_w<<<NN / 4, 256>>>((const uint2*)xw, (uint2*)h);

    // g = an @ h -> fp32
    k_spmm_a<<<NN / 4, 256>>>((const uint2*)h, (float4*)g);

    // z_mean = g @ Wm ; z_log_std = g @ Ws  (fp32 out)
    k_mma<HH, false, true, false><<<dim3(2, mtiles), 128>>>(g, Wm, Ws, out, NN, OO);
}